// round 3
// baseline (speedup 1.0000x reference)
#include <cuda_runtime.h>
#include <cstdint>
#include <cstddef>

// Problem constants
#define B_   256
#define F_   256
#define NJ3_ 51
#define IN_  34
#define D_   512
#define G4_  2048          // 4*D gates
#define KP_  576           // padded K for layer0 recurrent GEMM: 512 (h) + 51 (pred) + 13 zero
#define INITW_ 85          // NJ3 + IN_DIM

// ---------------- device scratch (static globals; no runtime alloc) ----------------
__device__ float g_G0x[(size_t)B_ * F_ * G4_];   // [t][b][g] precomputed input-path gates + biases (512MB)
__device__ float g_WxT[(size_t)D_ * G4_];        // Wih0[:, :512] transposed -> [k][g]
__device__ float g_Wc[IN_ * G4_];                // embed_W @ Wih0_x^T  (34 x 2048)
__device__ float g_bias0[G4_];
__device__ float g_bias1[G4_];
__device__ float g_W0p[G4_ * KP_];               // [Whh0 | Wih0_pred | 0]  (tf32-rounded)
__device__ float g_Wih1t[G4_ * D_];              // tf32-rounded copies
__device__ float g_Whh1t[G4_ * D_];
__device__ float g_decWt[NJ3_ * D_];             // dec_W transposed (n-major, k-contig)
__device__ float g_a0[2][B_ * KP_];              // ping-pong: [h0 (512) | pred (51) | zeros (13)]
__device__ float g_h1[2][B_ * D_];
__device__ float g_c0[B_ * D_];
__device__ float g_c1[B_ * D_];
__device__ float g_gbuf1[B_ * G4_];              // h1@Whh1^T partial
__device__ float g_z1[B_ * D_];
__device__ float g_z2[B_ * 1024];
__device__ float g_z3[B_ * G4_];

// ---------------- helpers ----------------
__device__ __forceinline__ uint32_t f2tf(float x) {
    uint32_t r; asm("cvt.rna.tf32.f32 %0, %1;" : "=r"(r) : "f"(x)); return r;
}
__device__ __forceinline__ void mma8(float (&c)[4], uint32_t a0, uint32_t a1, uint32_t a2, uint32_t a3,
                                     uint32_t b0, uint32_t b1) {
    asm volatile(
        "mma.sync.aligned.m16n8k8.row.col.f32.tf32.tf32.f32 "
        "{%0,%1,%2,%3},{%4,%5,%6,%7},{%8,%9},{%0,%1,%2,%3};"
        : "+f"(c[0]), "+f"(c[1]), "+f"(c[2]), "+f"(c[3])
        : "r"(a0), "r"(a1), "r"(a2), "r"(a3), "r"(b0), "r"(b1));
}
__device__ __forceinline__ float dev_sigm(float x) { return 1.0f / (1.0f + __expf(-x)); }
__device__ __forceinline__ float dev_tanh(float x) { return 2.0f / (1.0f + __expf(-2.0f * x)) - 1.0f; }

// Warp-level GEMM: computes C tile (64 rows x 8 d-cols x 4 gates) of A(256xK) @ W(2048xK)^T
// W row stride == K for all our weight buffers. m0 = row base, nd = d-col base for this warp.
__device__ __forceinline__ void mma_gemm_warp(const float* __restrict__ A, int lda,
                                              const float* __restrict__ W, int K,
                                              int m0, int nd, int lane, float (&c)[4][4][4]) {
    int qid = lane >> 2, qk = lane & 3;
    for (int k0 = 0; k0 < K; k0 += 8) {
        uint32_t af[4][4];
#pragma unroll
        for (int mt = 0; mt < 4; mt++) {
            const float* ap = A + (size_t)(m0 + mt * 16 + qid) * lda + k0 + qk;
            af[mt][0] = f2tf(__ldg(ap));
            af[mt][2] = f2tf(__ldg(ap + 4));
            af[mt][1] = f2tf(__ldg(ap + 8 * lda));
            af[mt][3] = f2tf(__ldg(ap + 8 * lda + 4));
        }
#pragma unroll
        for (int g = 0; g < 4; g++) {
            const float* bp = W + (size_t)(g * 512 + nd + qid) * K + k0 + qk;
            uint32_t b0 = __float_as_uint(__ldg(bp));
            uint32_t b1 = __float_as_uint(__ldg(bp + 4));
#pragma unroll
            for (int mt = 0; mt < 4; mt++)
                mma8(c[mt][g], af[mt][0], af[mt][1], af[mt][2], af[mt][3], b0, b1);
        }
    }
}

// ---------------- prep kernels ----------------
__global__ void transpose_wx(const float* __restrict__ Wih0) {
    __shared__ float tile[32][33];
    int g0 = blockIdx.x * 32, k0 = blockIdx.y * 32;
    int tx = threadIdx.x, ty = threadIdx.y;
    tile[ty][tx] = Wih0[(size_t)(g0 + ty) * 563 + k0 + tx];
    __syncthreads();
    g_WxT[(size_t)(k0 + ty) * G4_ + g0 + tx] = tile[tx][ty];
}

__global__ void prep_bias(const float* __restrict__ embed_b,
                          const float* __restrict__ bih0, const float* __restrict__ bhh0,
                          const float* __restrict__ bih1, const float* __restrict__ bhh1) {
    int g = blockIdx.x * blockDim.x + threadIdx.x;
    if (g >= G4_) return;
    float acc = bih0[g] + bhh0[g];
    for (int k = 0; k < D_; k++) acc += embed_b[k] * g_WxT[(size_t)k * G4_ + g];
    g_bias0[g] = acc;
    g_bias1[g] = bih1[g] + bhh1[g];
}

__global__ void prep_w0p(const float* __restrict__ Whh0, const float* __restrict__ Wih0) {
    int idx = blockIdx.x * blockDim.x + threadIdx.x;
    if (idx >= G4_ * KP_) return;
    int n = idx / KP_, k = idx % KP_;
    float v = 0.0f;
    if (k < 512) v = Whh0[(size_t)n * 512 + k];
    else if (k < 563) v = Wih0[(size_t)n * 563 + k];    // cols 512..562 of Wih0 = pred part
    g_W0p[idx] = __uint_as_float(f2tf(v));
}

__global__ void prep_round1(const float* __restrict__ Wih1, const float* __restrict__ Whh1) {
    int idx = blockIdx.x * blockDim.x + threadIdx.x;
    if (idx >= G4_ * D_) return;
    g_Wih1t[idx] = __uint_as_float(f2tf(Wih1[idx]));
    g_Whh1t[idx] = __uint_as_float(f2tf(Whh1[idx]));
}

__global__ void prep_dect(const float* __restrict__ dec_W) {
    int idx = blockIdx.x * blockDim.x + threadIdx.x;
    if (idx >= NJ3_ * D_) return;
    int n = idx / D_, k = idx % D_;
    g_decWt[idx] = dec_W[(size_t)k * NJ3_ + n];
}

// generic fp32 tiled GEMM: C = act(A(MxK) @ B(KxN) + bias)
__global__ void gemm_rm(const float* __restrict__ A, const float* __restrict__ Bm,
                        const float* __restrict__ bias, float* __restrict__ C,
                        int M, int N, int K, int relu) {
    __shared__ float sA[16][17], sB[16][17];
    int tx = threadIdx.x, ty = threadIdx.y;
    int row = blockIdx.y * 16 + ty;
    int col = blockIdx.x * 16 + tx;
    float acc = 0.0f;
    for (int k0 = 0; k0 < K; k0 += 16) {
        int ka = k0 + tx, kb = k0 + ty;
        sA[ty][tx] = (row < M && ka < K) ? A[(size_t)row * K + ka] : 0.0f;
        sB[ty][tx] = (kb < K && col < N) ? Bm[(size_t)kb * N + col] : 0.0f;
        __syncthreads();
#pragma unroll
        for (int kk = 0; kk < 16; kk++) acc += sA[ty][kk] * sB[kk][tx];
        __syncthreads();
    }
    if (row < M && col < N) {
        if (bias) acc += bias[col];
        if (relu) acc = fmaxf(acc, 0.0f);
        C[(size_t)row * N + col] = acc;
    }
}

// G0x[t][b][g] = x[b][t][:] @ Wc + bias0[g]
__global__ void g0x_kernel(const float* __restrict__ x) {
    __shared__ float xs[16][IN_];
    int g = blockIdx.x * 128 + threadIdx.x;
    int r0 = blockIdx.y * 16;
    for (int idx = threadIdx.x; idx < 16 * IN_; idx += 128) {
        int rr = idx / IN_, i = idx % IN_;
        xs[rr][i] = x[(size_t)(r0 + rr) * IN_ + i];
    }
    __syncthreads();
    float acc[16];
    float b0v = g_bias0[g];
#pragma unroll
    for (int rr = 0; rr < 16; rr++) acc[rr] = b0v;
    for (int i = 0; i < IN_; i++) {
        float wv = g_Wc[(size_t)i * G4_ + g];
#pragma unroll
        for (int rr = 0; rr < 16; rr++) acc[rr] += xs[rr][i] * wv;
    }
#pragma unroll
    for (int rr = 0; rr < 16; rr++) {
        int r = r0 + rr;
        int b = r >> 8, tt = r & 255;
        g_G0x[((size_t)tt * B_ + b) * G4_ + g] = acc[rr];
    }
}

// scatter init MLP result + pred0 into state buffers
__global__ void init_state(const float* __restrict__ initv) {
    int b = blockIdx.x, tid = threadIdx.x;
    if (tid < 512) {
        g_a0[0][(size_t)b * KP_ + tid] = g_z3[(size_t)b * G4_ + tid];          // h layer0
        g_h1[0][(size_t)b * D_ + tid]  = g_z3[(size_t)b * G4_ + 512 + tid];    // h layer1
        g_c0[(size_t)b * D_ + tid]     = g_z3[(size_t)b * G4_ + 1024 + tid];   // c layer0
        g_c1[(size_t)b * D_ + tid]     = g_z3[(size_t)b * G4_ + 1536 + tid];   // c layer1
    } else if (tid < 563) {
        g_a0[0][(size_t)b * KP_ + tid] = initv[(size_t)b * INITW_ + (tid - 512)];   // pred0
    } else if (tid < KP_) {
        g_a0[0][(size_t)b * KP_ + tid] = 0.0f;
        g_a0[1][(size_t)b * KP_ + tid] = 0.0f;
    }
}

// ---------------- per-step kernels ----------------
// K1: z=0: gates0 = G0x[t] + [h0|pred] @ W0p^T, LSTM0 elementwise -> h0n, c0
//     z=1: gbuf1 = h1 @ Whh1^T + bias1
__global__ void __launch_bounds__(128) step_k1(int t, int p) {
    int w = threadIdx.x >> 5, lane = threadIdx.x & 31;
    int qid = lane >> 2, qk = lane & 3;
    int m0 = blockIdx.y * 64;
    int nd = blockIdx.x * 32 + w * 8;
    float c[4][4][4];
#pragma unroll
    for (int a = 0; a < 4; a++)
#pragma unroll
        for (int b = 0; b < 4; b++)
#pragma unroll
            for (int e = 0; e < 4; e++) c[a][b][e] = 0.0f;

    if (blockIdx.z == 0) {
        mma_gemm_warp(g_a0[p], KP_, g_W0p, KP_, m0, nd, lane, c);
#pragma unroll
        for (int mt = 0; mt < 4; mt++)
#pragma unroll
            for (int ci = 0; ci < 4; ci++) {
                int r = m0 + mt * 16 + qid + ((ci >> 1) << 3);
                int d = nd + 2 * qk + (ci & 1);
                size_t gb = ((size_t)t * B_ + r) * G4_;
                float vi = c[mt][0][ci] + g_G0x[gb + d];
                float vf = c[mt][1][ci] + g_G0x[gb + 512 + d];
                float vg = c[mt][2][ci] + g_G0x[gb + 1024 + d];
                float vo = c[mt][3][ci] + g_G0x[gb + 1536 + d];
                float cold = g_c0[(size_t)r * D_ + d];
                float cn = dev_sigm(vf) * cold + dev_sigm(vi) * dev_tanh(vg);
                float hn = dev_sigm(vo) * dev_tanh(cn);
                g_c0[(size_t)r * D_ + d] = cn;
                g_a0[p ^ 1][(size_t)r * KP_ + d] = hn;
            }
    } else {
        mma_gemm_warp(g_h1[p], D_, g_Whh1t, D_, m0, nd, lane, c);
#pragma unroll
        for (int mt = 0; mt < 4; mt++)
#pragma unroll
            for (int ci = 0; ci < 4; ci++) {
                int r = m0 + mt * 16 + qid + ((ci >> 1) << 3);
                int d = nd + 2 * qk + (ci & 1);
#pragma unroll
                for (int g = 0; g < 4; g++)
                    g_gbuf1[(size_t)r * G4_ + g * 512 + d] = c[mt][g][ci] + g_bias1[g * 512 + d];
            }
    }
}

// K2: gates1 = gbuf1 + h0n @ Wih1^T, LSTM1 elementwise -> h1n, c1; write ctx output
__global__ void __launch_bounds__(128) step_k2(int t, int p, float* __restrict__ mc) {
    int w = threadIdx.x >> 5, lane = threadIdx.x & 31;
    int qid = lane >> 2, qk = lane & 3;
    int m0 = blockIdx.y * 64;
    int nd = blockIdx.x * 32 + w * 8;
    float c[4][4][4];
#pragma unroll
    for (int a = 0; a < 4; a++)
#pragma unroll
        for (int b = 0; b < 4; b++)
#pragma unroll
            for (int e = 0; e < 4; e++) c[a][b][e] = 0.0f;

    mma_gemm_warp(g_a0[p ^ 1], KP_, g_Wih1t, D_, m0, nd, lane, c);  // A = h0n (cols 0..511)
#pragma unroll
    for (int mt = 0; mt < 4; mt++)
#pragma unroll
        for (int ci = 0; ci < 4; ci++) {
            int r = m0 + mt * 16 + qid + ((ci >> 1) << 3);
            int d = nd + 2 * qk + (ci & 1);
            size_t gb = (size_t)r * G4_;
            float vi = c[mt][0][ci] + g_gbuf1[gb + d];
            float vf = c[mt][1][ci] + g_gbuf1[gb + 512 + d];
            float vg = c[mt][2][ci] + g_gbuf1[gb + 1024 + d];
            float vo = c[mt][3][ci] + g_gbuf1[gb + 1536 + d];
            float cold = g_c1[(size_t)r * D_ + d];
            float cn = dev_sigm(vf) * cold + dev_sigm(vi) * dev_tanh(vg);
            float hn = dev_sigm(vo) * dev_tanh(cn);
            g_c1[(size_t)r * D_ + d] = cn;
            g_h1[p ^ 1][(size_t)r * D_ + d] = hn;
            mc[((size_t)r * F_ + t) * 563 + d] = hn;   // motion_context ctx part
        }
}

// K3: pred = h1n @ dec_W + dec_b ; feed back + write outputs
__global__ void __launch_bounds__(256) step_k3(int t, int p, float* __restrict__ mc,
                                               float* __restrict__ kp, const float* __restrict__ dec_b) {
    __shared__ float sh[8][D_];
    int r0 = blockIdx.x * 8;
    for (int idx = threadIdx.x; idx < 8 * D_; idx += 256) {
        int rr = idx >> 9, k = idx & 511;
        sh[rr][k] = g_h1[p ^ 1][(size_t)(r0 + rr) * D_ + k];
    }
    __syncthreads();
    for (int oi = threadIdx.x; oi < 8 * NJ3_; oi += 256) {
        int rr = oi / NJ3_, n = oi % NJ3_;
        float acc = dec_b[n];
        const float* wt = g_decWt + (size_t)n * D_;
        const float* hr = sh[rr];
#pragma unroll 8
        for (int k = 0; k < D_; k++) acc += hr[k] * wt[k];
        int r = r0 + rr;
        g_a0[p ^ 1][(size_t)r * KP_ + 512 + n] = acc;          // feedback into next step input
        mc[((size_t)r * F_ + t) * 563 + 512 + n] = acc;        // motion_context pred part
        kp[((size_t)r * F_ + t) * NJ3_ + n] = acc;             // pred_kp3d
    }
}

// ---------------- host launcher ----------------
extern "C" void kernel_launch(void* const* d_in, const int* in_sizes, int n_in,
                              void* d_out, int out_size) {
    const float* x       = (const float*)d_in[0];
    const float* initv   = (const float*)d_in[1];
    const float* embed_W = (const float*)d_in[2];
    const float* embed_b = (const float*)d_in[3];
    const float* ni_W1   = (const float*)d_in[4];
    const float* ni_b1   = (const float*)d_in[5];
    const float* ni_W2   = (const float*)d_in[6];
    const float* ni_b2   = (const float*)d_in[7];
    const float* ni_W3   = (const float*)d_in[8];
    const float* ni_b3   = (const float*)d_in[9];
    const float* Wih0    = (const float*)d_in[10];
    const float* Whh0    = (const float*)d_in[11];
    const float* bih0    = (const float*)d_in[12];
    const float* bhh0    = (const float*)d_in[13];
    const float* Wih1    = (const float*)d_in[14];
    const float* Whh1    = (const float*)d_in[15];
    const float* bih1    = (const float*)d_in[16];
    const float* bhh1    = (const float*)d_in[17];
    const float* dec_W   = (const float*)d_in[18];
    const float* dec_b   = (const float*)d_in[19];

    float* kp_out = (float*)d_out;
    float* mc_out = kp_out + (size_t)B_ * F_ * NJ3_;

    float *pWxT, *pWc, *pz1, *pz2, *pz3;
    cudaGetSymbolAddress((void**)&pWxT, g_WxT);
    cudaGetSymbolAddress((void**)&pWc, g_Wc);
    cudaGetSymbolAddress((void**)&pz1, g_z1);
    cudaGetSymbolAddress((void**)&pz2, g_z2);
    cudaGetSymbolAddress((void**)&pz3, g_z3);

    // ---- prep (one-time per call; all capture-safe kernel launches) ----
    transpose_wx<<<dim3(64, 16), dim3(32, 32)>>>(Wih0);
    gemm_rm<<<dim3(G4_ / 16, (IN_ + 15) / 16), dim3(16, 16)>>>(embed_W, pWxT, nullptr, pWc, IN_, G4_, D_, 0);
    prep_bias<<<G4_ / 256, 256>>>(embed_b, bih0, bhh0, bih1, bhh1);
    prep_w0p<<<(G4_ * KP_ + 255) / 256, 256>>>(Whh0, Wih0);
    prep_round1<<<(G4_ * D_ + 255) / 256, 256>>>(Wih1, Whh1);
    prep_dect<<<(NJ3_ * D_ + 255) / 256, 256>>>(dec_W);
    g0x_kernel<<<dim3(16, (B_ * F_) / 16), 128>>>(x);

    // ---- init MLP -> h0/c0/h1/c1/pred0 ----
    gemm_rm<<<dim3(D_ / 16, B_ / 16), dim3(16, 16)>>>(initv, ni_W1, ni_b1, pz1, B_, D_, INITW_, 1);
    gemm_rm<<<dim3(1024 / 16, B_ / 16), dim3(16, 16)>>>(pz1, ni_W2, ni_b2, pz2, B_, 1024, D_, 1);
    gemm_rm<<<dim3(G4_ / 16, B_ / 16), dim3(16, 16)>>>(pz2, ni_W3, ni_b3, pz3, B_, G4_, 1024, 0);
    init_state<<<B_, KP_>>>(initv);

    // ---- 256 sequential LSTM steps ----
    for (int t = 0; t < F_; t++) {
        int p = t & 1;
        step_k1<<<dim3(16, 4, 2), 128>>>(t, p);
        step_k2<<<dim3(16, 4, 1), 128>>>(t, p, mc_out);
        step_k3<<<B_ / 8, 256>>>(t, p, mc_out, kp_out, dec_b);
    }
}

// round 7
// speedup vs baseline: 1.4791x; 1.4791x over previous
#include <cuda_runtime.h>
#include <cstdint>
#include <cstddef>

// Problem constants
#define B_   256
#define F_   256
#define NJ3_ 51
#define IN_  34
#define D_   512
#define G4_  2048          // 4*D gates
#define KP_  576           // padded K for layer0 recurrent GEMM: 512 (h) + 51 (pred) + 13 zero
#define INITW_ 85          // NJ3 + IN_DIM
#define SST  36            // smem tile k-stride (conflict-free: bank = 4*qid+qk)

// ---------------- device scratch (static globals; no runtime alloc) ----------------
__device__ float g_G0x[(size_t)B_ * F_ * G4_];   // [t][b][g] precomputed input-path gates + biases
__device__ float g_WxT[(size_t)D_ * G4_];        // Wih0[:, :512] transposed -> [k][g]
__device__ float g_Wc[IN_ * G4_];                // embed_W @ Wih0_x^T  (34 x 2048)
__device__ float g_bias0[G4_];
__device__ float g_bias1[G4_];
__device__ float g_W0p[G4_ * KP_];               // [Whh0 | Wih0_pred | 0]  (tf32-rounded), n-major k-contig
__device__ float g_Wih1t[G4_ * D_];              // tf32-rounded
__device__ float g_Whh1t[G4_ * D_];
__device__ float g_decWt[NJ3_ * D_];             // dec_W transposed (n-major, k-contig)
__device__ float g_a0[2][B_ * KP_];              // ping-pong: [h0 (512) | pred (51) | zeros (13)] (tf32-rounded)
__device__ float g_h1[2][B_ * D_];               // tf32-rounded h1
__device__ float g_c0[B_ * D_];
__device__ float g_c1[B_ * D_];
__device__ float g_gbuf1[B_ * G4_];              // h1@Whh1^T partial + bias1
__device__ float g_z1[B_ * D_];
__device__ float g_z2[B_ * 1024];
__device__ float g_z3[B_ * G4_];

// ---------------- helpers ----------------
__device__ __forceinline__ uint32_t f2tf(float x) {
    uint32_t r; asm("cvt.rna.tf32.f32 %0, %1;" : "=r"(r) : "f"(x)); return r;
}
__device__ __forceinline__ void mma8(float (&c)[4], uint32_t a0, uint32_t a1, uint32_t a2, uint32_t a3,
                                     uint32_t b0, uint32_t b1) {
    asm volatile(
        "mma.sync.aligned.m16n8k8.row.col.f32.tf32.tf32.f32 "
        "{%0,%1,%2,%3},{%4,%5,%6,%7},{%8,%9},{%0,%1,%2,%3};"
        : "+f"(c[0]), "+f"(c[1]), "+f"(c[2]), "+f"(c[3])
        : "r"(a0), "r"(a1), "r"(a2), "r"(a3), "r"(b0), "r"(b1));
}
__device__ __forceinline__ float dev_sigm(float x) { return 1.0f / (1.0f + __expf(-x)); }
__device__ __forceinline__ float dev_tanh(float x) { return 2.0f / (1.0f + __expf(-2.0f * x)) - 1.0f; }

__device__ __forceinline__ void cp16(float* smem_dst, const float* gsrc) {
    uint32_t s = (uint32_t)__cvta_generic_to_shared(smem_dst);
    asm volatile("cp.async.cg.shared.global [%0], [%1], 16;" :: "r"(s), "l"(gsrc) : "memory");
}

// Load one 64x32 A tile and one 64x32 B tile (B rows: gate*16 + dlocal) into smem.
__device__ __forceinline__ void load_tiles(float* sa, float* sb,
                                           const float* __restrict__ A, int lda,
                                           const float* __restrict__ W, int ldw,
                                           int m0, int d0, int k0, int tid) {
#pragma unroll 2
    for (int u = tid; u < 512; u += 256) {
        int row = u >> 3, kf = (u & 7) << 2;
        cp16(sa + row * SST + kf, A + (size_t)(m0 + row) * lda + k0 + kf);
    }
#pragma unroll 2
    for (int u = tid; u < 512; u += 256) {
        int rp = u >> 3, kf = (u & 7) << 2;
        int g = rp >> 4, dl = rp & 15;
        cp16(sb + rp * SST + kf, W + (size_t)((g << 9) + d0 + dl) * ldw + k0 + kf);
    }
    asm volatile("cp.async.commit_group;\n" ::: "memory");
}

// Double-buffered GEMM over K = KN*32. Produces c[gate][ci] for this warp's
// 16 rows x 8 d-cols x 4 gates subtile. Warp layout: wm = w>>1 (m16 group),
// wd = w&1 (d8 group). Activations in A are pre-rounded to tf32.
__device__ __forceinline__ void gemm_tile(float (&c)[4][4], float* sA, float* sB,
                                          const float* __restrict__ A, int lda,
                                          const float* __restrict__ W, int ldw,
                                          int m0, int d0, int KN,
                                          int tid, int wm, int wd, int qid, int qk) {
    load_tiles(sA, sB, A, lda, W, ldw, m0, d0, 0, tid);
    for (int ch = 0; ch < KN; ch++) {
        if (ch + 1 < KN) {
            load_tiles(sA + ((ch + 1) & 1) * (64 * SST), sB + ((ch + 1) & 1) * (64 * SST),
                       A, lda, W, ldw, m0, d0, (ch + 1) * 32, tid);
            asm volatile("cp.async.wait_group 1;\n" ::: "memory");
        } else {
            asm volatile("cp.async.wait_group 0;\n" ::: "memory");
        }
        __syncthreads();
        const float* pa = sA + (ch & 1) * (64 * SST);
        const float* pb = sB + (ch & 1) * (64 * SST);
#pragma unroll
        for (int kk = 0; kk < 32; kk += 8) {
            uint32_t a0 = __float_as_uint(pa[(wm * 16 + qid) * SST + kk + qk]);
            uint32_t a1 = __float_as_uint(pa[(wm * 16 + qid + 8) * SST + kk + qk]);
            uint32_t a2 = __float_as_uint(pa[(wm * 16 + qid) * SST + kk + qk + 4]);
            uint32_t a3 = __float_as_uint(pa[(wm * 16 + qid + 8) * SST + kk + qk + 4]);
#pragma unroll
            for (int g = 0; g < 4; g++) {
                uint32_t b0 = __float_as_uint(pb[(g * 16 + wd * 8 + qid) * SST + kk + qk]);
                uint32_t b1 = __float_as_uint(pb[(g * 16 + wd * 8 + qid) * SST + kk + qk + 4]);
                mma8(c[g], a0, a1, a2, a3, b0, b1);
            }
        }
        __syncthreads();
    }
}

// ---------------- prep kernels ----------------
__global__ void transpose_wx(const float* __restrict__ Wih0) {
    __shared__ float tile[32][33];
    int g0 = blockIdx.x * 32, k0 = blockIdx.y * 32;
    int tx = threadIdx.x, ty = threadIdx.y;
    tile[ty][tx] = Wih0[(size_t)(g0 + ty) * 563 + k0 + tx];
    __syncthreads();
    g_WxT[(size_t)(k0 + ty) * G4_ + g0 + tx] = tile[tx][ty];
}

__global__ void prep_bias(const float* __restrict__ embed_b,
                          const float* __restrict__ bih0, const float* __restrict__ bhh0,
                          const float* __restrict__ bih1, const float* __restrict__ bhh1) {
    int g = blockIdx.x * blockDim.x + threadIdx.x;
    if (g >= G4_) return;
    float acc = bih0[g] + bhh0[g];
    for (int k = 0; k < D_; k++) acc += embed_b[k] * g_WxT[(size_t)k * G4_ + g];
    g_bias0[g] = acc;
    g_bias1[g] = bih1[g] + bhh1[g];
}

__global__ void prep_w0p(const float* __restrict__ Whh0, const float* __restrict__ Wih0) {
    int idx = blockIdx.x * blockDim.x + threadIdx.x;
    if (idx >= G4_ * KP_) return;
    int n = idx / KP_, k = idx % KP_;
    float v = 0.0f;
    if (k < 512) v = Whh0[(size_t)n * 512 + k];
    else if (k < 563) v = Wih0[(size_t)n * 563 + k];
    g_W0p[idx] = __uint_as_float(f2tf(v));
}

__global__ void prep_round1(const float* __restrict__ Wih1, const float* __restrict__ Whh1) {
    int idx = blockIdx.x * blockDim.x + threadIdx.x;
    if (idx >= G4_ * D_) return;
    g_Wih1t[idx] = __uint_as_float(f2tf(Wih1[idx]));
    g_Whh1t[idx] = __uint_as_float(f2tf(Whh1[idx]));
}

__global__ void prep_dect(const float* __restrict__ dec_W) {
    int idx = blockIdx.x * blockDim.x + threadIdx.x;
    if (idx >= NJ3_ * D_) return;
    int n = idx / D_, k = idx % D_;
    g_decWt[idx] = dec_W[(size_t)k * NJ3_ + n];
}

// generic fp32 tiled GEMM: C = act(A(MxK) @ B(KxN) + bias)
__global__ void gemm_rm(const float* __restrict__ A, const float* __restrict__ Bm,
                        const float* __restrict__ bias, float* __restrict__ C,
                        int M, int N, int K, int relu) {
    __shared__ float sA[16][17], sB[16][17];
    int tx = threadIdx.x, ty = threadIdx.y;
    int row = blockIdx.y * 16 + ty;
    int col = blockIdx.x * 16 + tx;
    float acc = 0.0f;
    for (int k0 = 0; k0 < K; k0 += 16) {
        int ka = k0 + tx, kb = k0 + ty;
        sA[ty][tx] = (row < M && ka < K) ? A[(size_t)row * K + ka] : 0.0f;
        sB[ty][tx] = (kb < K && col < N) ? Bm[(size_t)kb * N + col] : 0.0f;
        __syncthreads();
#pragma unroll
        for (int kk = 0; kk < 16; kk++) acc += sA[ty][kk] * sB[kk][tx];
        __syncthreads();
    }
    if (row < M && col < N) {
        if (bias) acc += bias[col];
        if (relu) acc = fmaxf(acc, 0.0f);
        C[(size_t)row * N + col] = acc;
    }
}

// G0x[t][b][g] = x[b][t][:] @ Wc + bias0[g]
__global__ void g0x_kernel(const float* __restrict__ x) {
    __shared__ float xs[16][IN_];
    int g = blockIdx.x * 128 + threadIdx.x;
    int r0 = blockIdx.y * 16;
    for (int idx = threadIdx.x; idx < 16 * IN_; idx += 128) {
        int rr = idx / IN_, i = idx % IN_;
        xs[rr][i] = x[(size_t)(r0 + rr) * IN_ + i];
    }
    __syncthreads();
    float acc[16];
    float b0v = g_bias0[g];
#pragma unroll
    for (int rr = 0; rr < 16; rr++) acc[rr] = b0v;
    for (int i = 0; i < IN_; i++) {
        float wv = g_Wc[(size_t)i * G4_ + g];
#pragma unroll
        for (int rr = 0; rr < 16; rr++) acc[rr] += xs[rr][i] * wv;
    }
#pragma unroll
    for (int rr = 0; rr < 16; rr++) {
        int r = r0 + rr;
        int b = r >> 8, tt = r & 255;
        g_G0x[((size_t)tt * B_ + b) * G4_ + g] = acc[rr];
    }
}

// scatter init MLP result + pred0 into state buffers (activations pre-rounded to tf32)
__global__ void init_state(const float* __restrict__ initv) {
    int b = blockIdx.x, tid = threadIdx.x;
    if (tid < 512) {
        g_a0[0][(size_t)b * KP_ + tid] = __uint_as_float(f2tf(g_z3[(size_t)b * G4_ + tid]));
        g_h1[0][(size_t)b * D_ + tid]  = __uint_as_float(f2tf(g_z3[(size_t)b * G4_ + 512 + tid]));
        g_c0[(size_t)b * D_ + tid]     = g_z3[(size_t)b * G4_ + 1024 + tid];
        g_c1[(size_t)b * D_ + tid]     = g_z3[(size_t)b * G4_ + 1536 + tid];
    } else if (tid < 563) {
        g_a0[0][(size_t)b * KP_ + tid] = __uint_as_float(f2tf(initv[(size_t)b * INITW_ + (tid - 512)]));
    } else if (tid < KP_) {
        g_a0[0][(size_t)b * KP_ + tid] = 0.0f;
        g_a0[1][(size_t)b * KP_ + tid] = 0.0f;
    }
}

// ---------------- per-step kernels ----------------
// K1: z=0: gates0 = G0x[t] + [h0|pred] @ W0p^T -> LSTM0 elementwise -> h0n (rounded), c0
//     z=1: gbuf1 = h1 @ Whh1^T + bias1
__global__ void __launch_bounds__(256) step_k1(int t, int p) {
    __shared__ float sA[2 * 64 * SST];
    __shared__ float sB[2 * 64 * SST];
    int tid = threadIdx.x;
    int w = tid >> 5, lane = tid & 31;
    int qid = lane >> 2, qk = lane & 3;
    int wm = w >> 1, wd = w & 1;
    int m0 = blockIdx.y * 64;
    int d0 = blockIdx.x * 16;

    float c[4][4];
#pragma unroll
    for (int g = 0; g < 4; g++)
#pragma unroll
        for (int e = 0; e < 4; e++) c[g][e] = 0.0f;

    if (blockIdx.z == 0) {
        gemm_tile(c, sA, sB, g_a0[p], KP_, g_W0p, KP_, m0, d0, 18, tid, wm, wd, qid, qk);
        int rbase = m0 + wm * 16 + qid;
        int dbase = d0 + wd * 8 + 2 * qk;
#pragma unroll
        for (int ci = 0; ci < 4; ci++) {
            int r = rbase + ((ci >> 1) << 3);
            int d = dbase + (ci & 1);
            size_t gb = ((size_t)t * B_ + r) * G4_ + d;
            float vi = c[0][ci] + g_G0x[gb];
            float vf = c[1][ci] + g_G0x[gb + 512];
            float vg = c[2][ci] + g_G0x[gb + 1024];
            float vo = c[3][ci] + g_G0x[gb + 1536];
            float cold = g_c0[(size_t)r * D_ + d];
            float cn = dev_sigm(vf) * cold + dev_sigm(vi) * dev_tanh(vg);
            float hn = dev_sigm(vo) * dev_tanh(cn);
            g_c0[(size_t)r * D_ + d] = cn;
            g_a0[p ^ 1][(size_t)r * KP_ + d] = __uint_as_float(f2tf(hn));
        }
    } else {
        gemm_tile(c, sA, sB, g_h1[p], D_, g_Whh1t, D_, m0, d0, 16, tid, wm, wd, qid, qk);
        int rbase = m0 + wm * 16 + qid;
        int dbase = d0 + wd * 8 + 2 * qk;
#pragma unroll
        for (int ci = 0; ci < 4; ci++) {
            int r = rbase + ((ci >> 1) << 3);
            int d = dbase + (ci & 1);
#pragma unroll
            for (int g = 0; g < 4; g++)
                g_gbuf1[(size_t)r * G4_ + g * 512 + d] = c[g][ci] + g_bias1[g * 512 + d];
        }
    }
}

// K2: gates1 = gbuf1 + h0n @ Wih1^T -> LSTM1 elementwise -> h1n (rounded), c1; mc ctx (full)
__global__ void __launch_bounds__(256) step_k2(int t, int p, float* __restrict__ mc) {
    __shared__ float sA[2 * 64 * SST];
    __shared__ float sB[2 * 64 * SST];
    int tid = threadIdx.x;
    int w = tid >> 5, lane = tid & 31;
    int qid = lane >> 2, qk = lane & 3;
    int wm = w >> 1, wd = w & 1;
    int m0 = blockIdx.y * 64;
    int d0 = blockIdx.x * 16;

    float c[4][4];
#pragma unroll
    for (int g = 0; g < 4; g++)
#pragma unroll
        for (int e = 0; e < 4; e++) c[g][e] = 0.0f;

    gemm_tile(c, sA, sB, g_a0[p ^ 1], KP_, g_Wih1t, D_, m0, d0, 16, tid, wm, wd, qid, qk);

    int rbase = m0 + wm * 16 + qid;
    int dbase = d0 + wd * 8 + 2 * qk;
#pragma unroll
    for (int ci = 0; ci < 4; ci++) {
        int r = rbase + ((ci >> 1) << 3);
        int d = dbase + (ci & 1);
        size_t gb = (size_t)r * G4_;
        float vi = c[0][ci] + g_gbuf1[gb + d];
        float vf = c[1][ci] + g_gbuf1[gb + 512 + d];
        float vg = c[2][ci] + g_gbuf1[gb + 1024 + d];
        float vo = c[3][ci] + g_gbuf1[gb + 1536 + d];
        float cold = g_c1[(size_t)r * D_ + d];
        float cn = dev_sigm(vf) * cold + dev_sigm(vi) * dev_tanh(vg);
        float hn = dev_sigm(vo) * dev_tanh(cn);
        g_c1[(size_t)r * D_ + d] = cn;
        g_h1[p ^ 1][(size_t)r * D_ + d] = __uint_as_float(f2tf(hn));
        mc[((size_t)r * F_ + t) * 563 + d] = hn;     // full precision ctx
    }
}

// K3: pred = h1n @ dec_W + dec_b; feedback (rounded) + outputs (full).
// Reads full-precision h1n back from mc (written by K2 this step).
__global__ void __launch_bounds__(256) step_k3(int t, int p, float* __restrict__ mc,
                                               float* __restrict__ kp, const float* __restrict__ dec_b) {
    __shared__ float sh[8][D_];
    int r0 = blockIdx.x * 8;
    for (int idx = threadIdx.x; idx < 8 * D_; idx += 256) {
        int rr = idx >> 9, k = idx & 511;
        sh[rr][k] = mc[((size_t)(r0 + rr) * F_ + t) * 563 + k];
    }
    __syncthreads();
    for (int oi = threadIdx.x; oi < 8 * NJ3_; oi += 256) {
        int rr = oi / NJ3_, n = oi % NJ3_;
        float acc = dec_b[n];
        const float* wt = g_decWt + (size_t)n * D_;
        const float* hr = sh[rr];
#pragma unroll 8
        for (int k = 0; k < D_; k++) acc += hr[k] * wt[k];
        int r = r0 + rr;
        g_a0[p ^ 1][(size_t)r * KP_ + 512 + n] = __uint_as_float(f2tf(acc));
        mc[((size_t)r * F_ + t) * 563 + 512 + n] = acc;
        kp[((size_t)r * F_ + t) * NJ3_ + n] = acc;
    }
}

// ---------------- host launcher ----------------
extern "C" void kernel_launch(void* const* d_in, const int* in_sizes, int n_in,
                              void* d_out, int out_size) {
    const float* x       = (const float*)d_in[0];
    const float* initv   = (const float*)d_in[1];
    const float* embed_W = (const float*)d_in[2];
    const float* embed_b = (const float*)d_in[3];
    const float* ni_W1   = (const float*)d_in[4];
    const float* ni_b1   = (const float*)d_in[5];
    const float* ni_W2   = (const float*)d_in[6];
    const float* ni_b2   = (const float*)d_in[7];
    const float* ni_W3   = (const float*)d_in[8];
    const float* ni_b3   = (const float*)d_in[9];
    const float* Wih0    = (const float*)d_in[10];
    const float* Whh0    = (const float*)d_in[11];
    const float* bih0    = (const float*)d_in[12];
    const float* bhh0    = (const float*)d_in[13];
    const float* Wih1    = (const float*)d_in[14];
    const float* Whh1    = (const float*)d_in[15];
    const float* bih1    = (const float*)d_in[16];
    const float* bhh1    = (const float*)d_in[17];
    const float* dec_W   = (const float*)d_in[18];
    const float* dec_b   = (const float*)d_in[19];

    float* kp_out = (float*)d_out;
    float* mc_out = kp_out + (size_t)B_ * F_ * NJ3_;

    float *pWxT, *pWc, *pz1, *pz2, *pz3;
    cudaGetSymbolAddress((void**)&pWxT, g_WxT);
    cudaGetSymbolAddress((void**)&pWc, g_Wc);
    cudaGetSymbolAddress((void**)&pz1, g_z1);
    cudaGetSymbolAddress((void**)&pz2, g_z2);
    cudaGetSymbolAddress((void**)&pz3, g_z3);

    // ---- prep ----
    transpose_wx<<<dim3(64, 16), dim3(32, 32)>>>(Wih0);
    gemm_rm<<<dim3(G4_ / 16, (IN_ + 15) / 16), dim3(16, 16)>>>(embed_W, pWxT, nullptr, pWc, IN_, G4_, D_, 0);
    prep_bias<<<G4_ / 256, 256>>>(embed_b, bih0, bhh0, bih1, bhh1);
    prep_w0p<<<(G4_ * KP_ + 255) / 256, 256>>>(Whh0, Wih0);
    prep_round1<<<(G4_ * D_ + 255) / 256, 256>>>(Wih1, Whh1);
    prep_dect<<<(NJ3_ * D_ + 255) / 256, 256>>>(dec_W);
    g0x_kernel<<<dim3(16, (B_ * F_) / 16), 128>>>(x);

    // ---- init MLP -> h0/c0/h1/c1/pred0 ----
    gemm_rm<<<dim3(D_ / 16, B_ / 16), dim3(16, 16)>>>(initv, ni_W1, ni_b1, pz1, B_, D_, INITW_, 1);
    gemm_rm<<<dim3(1024 / 16, B_ / 16), dim3(16, 16)>>>(pz1, ni_W2, ni_b2, pz2, B_, 1024, D_, 1);
    gemm_rm<<<dim3(G4_ / 16, B_ / 16), dim3(16, 16)>>>(pz2, ni_W3, ni_b3, pz3, B_, G4_, 1024, 0);
    init_state<<<B_, KP_>>>(initv);

    // ---- 256 sequential LSTM steps ----
    for (int t = 0; t < F_; t++) {
        int p = t & 1;
        step_k1<<<dim3(32, 4, 2), 256>>>(t, p);
        step_k2<<<dim3(32, 4, 1), 256>>>(t, p, mc_out);
        step_k3<<<B_ / 8, 256>>>(t, p, mc_out, kp_out, dec_b);
    }
}